// round 2
// baseline (speedup 1.0000x reference)
#include <cuda_runtime.h>
#include <cuda_bf16.h>

// Output depends only on per-graph means of ORIGINAL node features + tiny MLP.
// (GraphConv layers in the reference are dead code — faithful DGL HeteroGraphConv
// bug: port1/net1/net2 are computed, deleted, never used.)

#define NGRAPHS 64
#define TPB 256
#define NODES_PER_BLOCK (TPB * 4)

// Scratch: sums [b*4 + col], col {comp:0, port:1,2, net:3}; counts [type*64 + b].
// Zero-initialized at module load; mlp_kernel restores zeros after reading,
// so the invariant holds across graph replays (no zero kernel needed).
__device__ float g_sum[NGRAPHS * 4];
__device__ float g_cnt[NGRAPHS * 3];

// Each thread handles 4 contiguous nodes (vectorized). One shot, no loop.
// Warp covers 128 contiguous nodes; gids sorted => almost always warp-uniform:
// shuffle-reduce + 1 shared atomic/warp. Boundary/tail warps: per-node atomics.
template <int COLS>
__device__ __forceinline__ void accum4(
    const float* __restrict__ x, const int* __restrict__ gid, int n,
    int node0, float* s_sum, float* s_cnt)
{
    const int i = node0 + threadIdx.x * 4;
    const bool full = (i + 3 < n);

    int g0 = 0;
    bool lu = false;          // locally uniform (4 nodes same gid)
    float ls[COLS];           // local per-col sums
#pragma unroll
    for (int c = 0; c < COLS; c++) ls[c] = 0.0f;

    if (full) {
        const int4 gv = *reinterpret_cast<const int4*>(gid + i);
        g0 = gv.x;
        lu = (gv.x == gv.y) & (gv.y == gv.z) & (gv.z == gv.w);
        if (COLS == 1) {
            const float4 xv = *reinterpret_cast<const float4*>(x + i);
            ls[0] = (xv.x + xv.y) + (xv.z + xv.w);
        } else {
            const float4 a = *reinterpret_cast<const float4*>(x + i * 2);
            const float4 b = *reinterpret_cast<const float4*>(x + i * 2 + 4);
            ls[0] = (a.x + a.z) + (b.x + b.z);
            if (COLS > 1) ls[1] = (a.y + a.w) + (b.y + b.w);
        }
    }

    const unsigned fm = __ballot_sync(0xffffffffu, full);
    const int gw = __shfl_sync(0xffffffffu, g0, 0);
    const bool uni = __all_sync(0xffffffffu, (!full) || (lu && g0 == gw));

    if (uni && fm) {
        // fm lanes form a prefix (contiguous layout), lane 0 is full.
#pragma unroll
        for (int c = 0; c < COLS; c++) {
            float s = ls[c];
#pragma unroll
            for (int off = 16; off > 0; off >>= 1)
                s += __shfl_xor_sync(0xffffffffu, s, off);
            if ((threadIdx.x & 31) == 0) atomicAdd(&s_sum[gw * COLS + c], s);
        }
        if ((threadIdx.x & 31) == 0)
            atomicAdd(&s_cnt[gw], 4.0f * (float)__popc(fm));
    } else {
        // slow path: per-node shared atomics (graph boundaries / tails only)
#pragma unroll
        for (int j = 0; j < 4; j++) {
            const int ii = i + j;
            if (ii < n) {
                const int g = gid[ii];
#pragma unroll
                for (int c = 0; c < COLS; c++)
                    atomicAdd(&s_sum[g * COLS + c], x[ii * COLS + c]);
                atomicAdd(&s_cnt[g], 1.0f);
            }
        }
    }
}

__global__ void accum_kernel(
    const float* __restrict__ h_comp, const int* __restrict__ gid_comp, int nc,
    const float* __restrict__ h_port, const int* __restrict__ gid_port, int np,
    const float* __restrict__ h_net,  const int* __restrict__ gid_net,  int nn,
    int nb_comp, int nb_port)
{
    __shared__ float s_sum[NGRAPHS * 2];
    __shared__ float s_cnt[NGRAPHS];
    const int tid = threadIdx.x;
    if (tid < NGRAPHS * 2) s_sum[tid] = 0.0f;
    if (tid < NGRAPHS) s_cnt[tid] = 0.0f;
    __syncthreads();

    const int blk = blockIdx.x;
    int type, cols, sum_off;
    if (blk < nb_comp) {
        accum4<1>(h_comp, gid_comp, nc, blk * NODES_PER_BLOCK, s_sum, s_cnt);
        type = 0; cols = 1; sum_off = 0;
    } else if (blk < nb_comp + nb_port) {
        accum4<2>(h_port, gid_port, np, (blk - nb_comp) * NODES_PER_BLOCK, s_sum, s_cnt);
        type = 1; cols = 2; sum_off = 1;
    } else {
        accum4<1>(h_net, gid_net, nn, (blk - nb_comp - nb_port) * NODES_PER_BLOCK, s_sum, s_cnt);
        type = 2; cols = 1; sum_off = 3;
    }
    __syncthreads();

    // Flush only touched graphs (a contiguous 1024-node block spans ~2-3 gids).
    if (tid < NGRAPHS && s_cnt[tid] != 0.0f) {
        atomicAdd(&g_cnt[type * NGRAPHS + tid], s_cnt[tid]);
        for (int c = 0; c < cols; c++)
            atomicAdd(&g_sum[tid * 4 + sum_off + c], s_sum[tid * cols + c]);
    }
}

// One block per graph, 128 threads. Also restores scratch to zero after reading
// (self-cleaning: keeps the zero-invariant for the next launch/replay).
__global__ void mlp_kernel(
    const float* __restrict__ Wc1, const float* __restrict__ bc1,
    const float* __restrict__ Wc2, const float* __restrict__ bc2,
    const float* __restrict__ Wc3, const float* __restrict__ bc3,
    float* __restrict__ out)
{
    const int b = blockIdx.x;
    const int j = threadIdx.x;  // 0..127
    __shared__ float tmp[7];    // [0..3]=sums, [4..6]=counts
    __shared__ float hg[4];
    __shared__ float h1[128];
    __shared__ float h2[128];

    if (j < 4) tmp[j] = g_sum[b * 4 + j];
    else if (j < 7) tmp[j] = g_cnt[(j - 4) * NGRAPHS + b];
    __syncthreads();
    // reset scratch for next call (all reads complete past the barrier)
    if (j < 4) g_sum[b * 4 + j] = 0.0f;
    else if (j < 7) g_cnt[(j - 4) * NGRAPHS + b] = 0.0f;

    if (j < 4) {
        const int type = (j == 0) ? 0 : (j < 3 ? 1 : 2);
        hg[j] = tmp[j] / fmaxf(tmp[4 + type], 1.0f);
    }
    __syncthreads();

    // layer 1: [4] -> [128]
    float a = bc1[j];
#pragma unroll
    for (int k = 0; k < 4; k++) a = fmaf(hg[k], Wc1[k * 128 + j], a);
    h1[j] = fmaxf(a, 0.0f);
    __syncthreads();

    // layer 2: [128] -> [128], coalesced L2-resident column reads
    float a0 = bc2[j], a1 = 0.0f, a2 = 0.0f, a3 = 0.0f;
#pragma unroll
    for (int k = 0; k < 128; k += 4) {
        a0 = fmaf(h1[k + 0], Wc2[(k + 0) * 128 + j], a0);
        a1 = fmaf(h1[k + 1], Wc2[(k + 1) * 128 + j], a1);
        a2 = fmaf(h1[k + 2], Wc2[(k + 2) * 128 + j], a2);
        a3 = fmaf(h1[k + 3], Wc2[(k + 3) * 128 + j], a3);
    }
    h2[j] = fmaxf((a0 + a1) + (a2 + a3), 0.0f);
    __syncthreads();

    // layer 3: [128] -> [10]
    if (j < 10) {
        float c0 = bc3[j], c1 = 0.0f, c2 = 0.0f, c3 = 0.0f;
#pragma unroll
        for (int k = 0; k < 128; k += 4) {
            c0 = fmaf(h2[k + 0], Wc3[(k + 0) * 10 + j], c0);
            c1 = fmaf(h2[k + 1], Wc3[(k + 1) * 10 + j], c1);
            c2 = fmaf(h2[k + 2], Wc3[(k + 2) * 10 + j], c2);
            c3 = fmaf(h2[k + 3], Wc3[(k + 3) * 10 + j], c3);
        }
        out[b * 10 + j] = (c0 + c1) + (c2 + c3);
    }
}

extern "C" void kernel_launch(void* const* d_in, const int* in_sizes, int n_in,
                              void* d_out, int out_size)
{
    const float* h_comp   = (const float*)d_in[0];
    const float* h_port   = (const float*)d_in[1];
    const float* h_net    = (const float*)d_in[2];
    // d_in[3..6] edges, d_in[10..21] conv weights: dead code in reference
    const int*   gid_comp = (const int*)d_in[7];
    const int*   gid_port = (const int*)d_in[8];
    const int*   gid_net  = (const int*)d_in[9];
    const float* Wc1 = (const float*)d_in[22];
    const float* bc1 = (const float*)d_in[23];
    const float* Wc2 = (const float*)d_in[24];
    const float* bc2 = (const float*)d_in[25];
    const float* Wc3 = (const float*)d_in[26];
    const float* bc3 = (const float*)d_in[27];

    const int nc = in_sizes[0];
    const int np = in_sizes[1] / 2;
    const int nn = in_sizes[2];

    const int nb_comp = (nc + NODES_PER_BLOCK - 1) / NODES_PER_BLOCK;
    const int nb_port = (np + NODES_PER_BLOCK - 1) / NODES_PER_BLOCK;
    const int nb_net  = (nn + NODES_PER_BLOCK - 1) / NODES_PER_BLOCK;

    accum_kernel<<<nb_comp + nb_port + nb_net, TPB>>>(
        h_comp, gid_comp, nc,
        h_port, gid_port, np,
        h_net,  gid_net,  nn,
        nb_comp, nb_port);
    mlp_kernel<<<NGRAPHS, 128>>>(Wc1, bc1, Wc2, bc2, Wc3, bc3, (float*)d_out);
}

// round 3
// speedup vs baseline: 1.0303x; 1.0303x over previous
#include <cuda_runtime.h>
#include <cuda_bf16.h>

// Output depends only on per-graph means of ORIGINAL node features + tiny MLP.
// (GraphConv layers in the reference are dead code — faithful DGL HeteroGraphConv
// bug: port1/net1/net2 are computed, deleted, never used.)

#define NGRAPHS 64
#define TPB 256
#define NODES_PER_BLOCK (TPB * 4)

// Scratch: sums [b*4 + col], col {comp:0, port:1,2, net:3}; counts [type*64 + b].
// Zero-initialized at module load; mlp_kernel restores zeros after reading,
// so the invariant holds across graph replays (no zero kernel needed).
__device__ float g_sum[NGRAPHS * 4];
__device__ float g_cnt[NGRAPHS * 3];

// Each thread handles 4 contiguous nodes (vectorized). One shot, no loop.
// Warp covers 128 contiguous nodes; gids sorted => almost always warp-uniform:
// shuffle-reduce + 1 shared atomic/warp. Boundary/tail warps: per-node atomics.
template <int COLS>
__device__ __forceinline__ void accum4(
    const float* __restrict__ x, const int* __restrict__ gid, int n,
    int node0, float* s_sum, float* s_cnt)
{
    const int i = node0 + threadIdx.x * 4;
    const bool full = (i + 3 < n);

    int g0 = 0;
    bool lu = false;          // locally uniform (4 nodes same gid)
    float ls[COLS];           // local per-col sums
#pragma unroll
    for (int c = 0; c < COLS; c++) ls[c] = 0.0f;

    if (full) {
        const int4 gv = *reinterpret_cast<const int4*>(gid + i);
        g0 = gv.x;
        lu = (gv.x == gv.y) & (gv.y == gv.z) & (gv.z == gv.w);
        if (COLS == 1) {
            const float4 xv = *reinterpret_cast<const float4*>(x + i);
            ls[0] = (xv.x + xv.y) + (xv.z + xv.w);
        } else {
            const float4 a = *reinterpret_cast<const float4*>(x + i * 2);
            const float4 b = *reinterpret_cast<const float4*>(x + i * 2 + 4);
            ls[0] = (a.x + a.z) + (b.x + b.z);
            if (COLS > 1) ls[1] = (a.y + a.w) + (b.y + b.w);
        }
    }

    const unsigned fm = __ballot_sync(0xffffffffu, full);
    const int gw = __shfl_sync(0xffffffffu, g0, 0);
    const bool uni = __all_sync(0xffffffffu, (!full) || (lu && g0 == gw));

    if (uni && fm) {
        // fm lanes form a prefix (contiguous layout), lane 0 is full.
#pragma unroll
        for (int c = 0; c < COLS; c++) {
            float s = ls[c];
#pragma unroll
            for (int off = 16; off > 0; off >>= 1)
                s += __shfl_xor_sync(0xffffffffu, s, off);
            if ((threadIdx.x & 31) == 0) atomicAdd(&s_sum[gw * COLS + c], s);
        }
        if ((threadIdx.x & 31) == 0)
            atomicAdd(&s_cnt[gw], 4.0f * (float)__popc(fm));
    } else {
        // slow path: per-node shared atomics (graph boundaries / tails only)
#pragma unroll
        for (int j = 0; j < 4; j++) {
            const int ii = i + j;
            if (ii < n) {
                const int g = gid[ii];
#pragma unroll
                for (int c = 0; c < COLS; c++)
                    atomicAdd(&s_sum[g * COLS + c], x[ii * COLS + c]);
                atomicAdd(&s_cnt[g], 1.0f);
            }
        }
    }
}

__global__ void accum_kernel(
    const float* __restrict__ h_comp, const int* __restrict__ gid_comp, int nc,
    const float* __restrict__ h_port, const int* __restrict__ gid_port, int np,
    const float* __restrict__ h_net,  const int* __restrict__ gid_net,  int nn,
    int nb_comp, int nb_port)
{
    __shared__ float s_sum[NGRAPHS * 2];
    __shared__ float s_cnt[NGRAPHS];
    const int tid = threadIdx.x;
    if (tid < NGRAPHS * 2) s_sum[tid] = 0.0f;
    if (tid < NGRAPHS) s_cnt[tid] = 0.0f;
    __syncthreads();

    const int blk = blockIdx.x;
    int type, cols, sum_off;
    if (blk < nb_comp) {
        accum4<1>(h_comp, gid_comp, nc, blk * NODES_PER_BLOCK, s_sum, s_cnt);
        type = 0; cols = 1; sum_off = 0;
    } else if (blk < nb_comp + nb_port) {
        accum4<2>(h_port, gid_port, np, (blk - nb_comp) * NODES_PER_BLOCK, s_sum, s_cnt);
        type = 1; cols = 2; sum_off = 1;
    } else {
        accum4<1>(h_net, gid_net, nn, (blk - nb_comp - nb_port) * NODES_PER_BLOCK, s_sum, s_cnt);
        type = 2; cols = 1; sum_off = 3;
    }
    __syncthreads();

    // Flush only touched graphs (a contiguous 1024-node block spans ~2-3 gids).
    if (tid < NGRAPHS && s_cnt[tid] != 0.0f) {
        atomicAdd(&g_cnt[type * NGRAPHS + tid], s_cnt[tid]);
        for (int c = 0; c < cols; c++)
            atomicAdd(&g_sum[tid * 4 + sum_off + c], s_sum[tid * cols + c]);
    }
}

// One block per graph, 128 threads. Also restores scratch to zero after reading
// (self-cleaning: keeps the zero-invariant for the next launch/replay).
__global__ void mlp_kernel(
    const float* __restrict__ Wc1, const float* __restrict__ bc1,
    const float* __restrict__ Wc2, const float* __restrict__ bc2,
    const float* __restrict__ Wc3, const float* __restrict__ bc3,
    float* __restrict__ out)
{
    const int b = blockIdx.x;
    const int j = threadIdx.x;  // 0..127
    __shared__ float tmp[7];    // [0..3]=sums, [4..6]=counts
    __shared__ float hg[4];
    __shared__ float h1[128];
    __shared__ float h2[128];

    if (j < 4) tmp[j] = g_sum[b * 4 + j];
    else if (j < 7) tmp[j] = g_cnt[(j - 4) * NGRAPHS + b];
    __syncthreads();
    // reset scratch for next call (all reads complete past the barrier)
    if (j < 4) g_sum[b * 4 + j] = 0.0f;
    else if (j < 7) g_cnt[(j - 4) * NGRAPHS + b] = 0.0f;

    if (j < 4) {
        const int type = (j == 0) ? 0 : (j < 3 ? 1 : 2);
        hg[j] = tmp[j] / fmaxf(tmp[4 + type], 1.0f);
    }
    __syncthreads();

    // layer 1: [4] -> [128]
    float a = bc1[j];
#pragma unroll
    for (int k = 0; k < 4; k++) a = fmaf(hg[k], Wc1[k * 128 + j], a);
    h1[j] = fmaxf(a, 0.0f);
    __syncthreads();

    // layer 2: [128] -> [128], coalesced L2-resident column reads
    float a0 = bc2[j], a1 = 0.0f, a2 = 0.0f, a3 = 0.0f;
#pragma unroll
    for (int k = 0; k < 128; k += 4) {
        a0 = fmaf(h1[k + 0], Wc2[(k + 0) * 128 + j], a0);
        a1 = fmaf(h1[k + 1], Wc2[(k + 1) * 128 + j], a1);
        a2 = fmaf(h1[k + 2], Wc2[(k + 2) * 128 + j], a2);
        a3 = fmaf(h1[k + 3], Wc2[(k + 3) * 128 + j], a3);
    }
    h2[j] = fmaxf((a0 + a1) + (a2 + a3), 0.0f);
    __syncthreads();

    // layer 3: [128] -> [10]
    if (j < 10) {
        float c0 = bc3[j], c1 = 0.0f, c2 = 0.0f, c3 = 0.0f;
#pragma unroll
        for (int k = 0; k < 128; k += 4) {
            c0 = fmaf(h2[k + 0], Wc3[(k + 0) * 10 + j], c0);
            c1 = fmaf(h2[k + 1], Wc3[(k + 1) * 10 + j], c1);
            c2 = fmaf(h2[k + 2], Wc3[(k + 2) * 10 + j], c2);
            c3 = fmaf(h2[k + 3], Wc3[(k + 3) * 10 + j], c3);
        }
        out[b * 10 + j] = (c0 + c1) + (c2 + c3);
    }
}

extern "C" void kernel_launch(void* const* d_in, const int* in_sizes, int n_in,
                              void* d_out, int out_size)
{
    const float* h_comp   = (const float*)d_in[0];
    const float* h_port   = (const float*)d_in[1];
    const float* h_net    = (const float*)d_in[2];
    // d_in[3..6] edges, d_in[10..21] conv weights: dead code in reference
    const int*   gid_comp = (const int*)d_in[7];
    const int*   gid_port = (const int*)d_in[8];
    const int*   gid_net  = (const int*)d_in[9];
    const float* Wc1 = (const float*)d_in[22];
    const float* bc1 = (const float*)d_in[23];
    const float* Wc2 = (const float*)d_in[24];
    const float* bc2 = (const float*)d_in[25];
    const float* Wc3 = (const float*)d_in[26];
    const float* bc3 = (const float*)d_in[27];

    const int nc = in_sizes[0];
    const int np = in_sizes[1] / 2;
    const int nn = in_sizes[2];

    const int nb_comp = (nc + NODES_PER_BLOCK - 1) / NODES_PER_BLOCK;
    const int nb_port = (np + NODES_PER_BLOCK - 1) / NODES_PER_BLOCK;
    const int nb_net  = (nn + NODES_PER_BLOCK - 1) / NODES_PER_BLOCK;

    accum_kernel<<<nb_comp + nb_port + nb_net, TPB>>>(
        h_comp, gid_comp, nc,
        h_port, gid_port, np,
        h_net,  gid_net,  nn,
        nb_comp, nb_port);
    mlp_kernel<<<NGRAPHS, 128>>>(Wc1, bc1, Wc2, bc2, Wc3, bc3, (float*)d_out);
}